// round 3
// baseline (speedup 1.0000x reference)
#include <cuda_runtime.h>
#include <cuda_fp16.h>
#include <cstdint>

// Problem dims
#define IN_F   4096
#define OUT_F  11008
#define MROWS  2048
#define NUMEL  (IN_F * OUT_F)        // 45,088,768
#define PACKED_N (NUMEL / 2)         // 22,544,384

// GEMM tiling
#define BM 128
#define BN 128
#define BK 64
#define KCHUNKS (IN_F / BK)          // 64
#define NST 3
#define A_BYTES (BM * 128)           // 16384 (128 rows x 128B)
#define B_BYTES (BN * 128)           // 16384
#define STAGE_BYTES (A_BYTES + B_BYTES)   // 32768
#define SMEM_BYTES (NST * STAGE_BYTES)    // 98304

// Scratch (device globals; no allocation allowed)
__device__ __half g_W[NUMEL];          // dequantized W, row-major [OUT_F][IN_F]
__device__ __half g_X[MROWS * IN_F];   // fp16 x

__constant__ float c_nf4[16] = {
    -1.0f, -0.6961928009986877f, -0.5250730514526367f, -0.39491748809814453f,
    -0.28444138169288635f, -0.18477343022823334f, -0.09105003625154495f, 0.0f,
    0.07958029955625534f, 0.16093020141124725f, 0.24611230194568634f,
    0.33791524171829224f, 0.44070982933044434f, 0.5626170039176941f,
    0.7229568362236023f, 1.0f};

// ---------------------------------------------------------------------------
// x fp32 -> fp16
// ---------------------------------------------------------------------------
__global__ void cvt_kernel(const float* __restrict__ x) {
    int i = blockIdx.x * blockDim.x + threadIdx.x;        // handles 4 floats
    float4 v = reinterpret_cast<const float4*>(x)[i];
    __half2* o = reinterpret_cast<__half2*>(g_X);
    o[2 * i]     = __floats2half2_rn(v.x, v.y);
    o[2 * i + 1] = __floats2half2_rn(v.z, v.w);
}

// ---------------------------------------------------------------------------
// NF4 dequant: each thread consumes 4 packed int32 (bytes) -> 8 fp16
// ---------------------------------------------------------------------------
__global__ void dequant_kernel(const int* __restrict__ packed,
                               const float* __restrict__ absmax) {
    int i = blockIdx.x * blockDim.x + threadIdx.x;        // handles packed[4i..4i+3]
    int4 pk = reinterpret_cast<const int4*>(packed)[i];
    float s = absmax[i >> 3];                              // (4i)/32 == i/8
    int v[4] = {pk.x, pk.y, pk.z, pk.w};
    __half h[8];
#pragma unroll
    for (int j = 0; j < 4; j++) {
        h[2 * j]     = __float2half_rn(c_nf4[(v[j] >> 4) & 0xF] * s);
        h[2 * j + 1] = __float2half_rn(c_nf4[v[j] & 0xF] * s);
    }
    reinterpret_cast<uint4*>(g_W)[i] = *reinterpret_cast<uint4*>(h);
}

// ---------------------------------------------------------------------------
// PTX helpers
// ---------------------------------------------------------------------------
__device__ __forceinline__ uint32_t smem_u32(const void* p) {
    uint32_t a;
    asm("{ .reg .u64 t; cvta.to.shared.u64 t, %1; cvt.u32.u64 %0, t; }"
        : "=r"(a) : "l"(p));
    return a;
}

__device__ __forceinline__ void cp16(uint32_t saddr, const void* gaddr) {
    asm volatile("cp.async.cg.shared.global [%0], [%1], 16;"
                 :: "r"(saddr), "l"(gaddr));
}

__device__ __forceinline__ void ldm_x4(uint32_t* r, uint32_t addr) {
    asm volatile("ldmatrix.sync.aligned.m8n8.x4.shared.b16 {%0,%1,%2,%3}, [%4];"
                 : "=r"(r[0]), "=r"(r[1]), "=r"(r[2]), "=r"(r[3]) : "r"(addr));
}

// fp16 accumulate mma: C(f16x2 pair) += A(f16) * B(f16)
__device__ __forceinline__ void mma16816_f16(uint32_t& c0, uint32_t& c1,
                                             const uint32_t* a,
                                             uint32_t b0, uint32_t b1) {
    asm volatile(
        "mma.sync.aligned.m16n8k16.row.col.f16.f16.f16.f16 "
        "{%0,%1}, {%2,%3,%4,%5}, {%6,%7}, {%0,%1};"
        : "+r"(c0), "+r"(c1)
        : "r"(a[0]), "r"(a[1]), "r"(a[2]), "r"(a[3]), "r"(b0), "r"(b1));
}

// ---------------------------------------------------------------------------
// GEMM: out[128,128] tile = A[128,K] * B[128,K]^T + bias.
// fp16 inputs, fp16 mma accumulation over K=32 segments, promoted to fp32
// registers every 2 k-steps. 512 threads = 16 warps in 4(m) x 4(n); warp
// tile 32x32. 3-stage cp.async ring, SW128-swizzled 128B smem rows.
// ---------------------------------------------------------------------------
__global__ void __launch_bounds__(512)
gemm_kernel(const float* __restrict__ bias, float* __restrict__ out) {
    extern __shared__ char smem[];
    const uint32_t sb = smem_u32(smem);
    const int tid = threadIdx.x;
    const int wid = tid >> 5;
    const int lane = tid & 31;
    const int warp_m = wid >> 2;          // 0..3 (32-row blocks)
    const int warp_n = wid & 3;           // 0..3 (32-col blocks)
    const int row0 = blockIdx.y * BM;
    const int col0 = blockIdx.x * BN;

    const __half* Ab = g_X + (size_t)row0 * IN_F;
    const __half* Bb = g_W + (size_t)col0 * IN_F;

    // cp.async of chunk c into stage c%3. Each tile = 128 rows x 128B,
    // 1024 16B units; 512 threads -> 2 units each per tile.
    auto issue = [&](int c) {
        const int s = c % NST;
        const int kc = c * BK;
        const uint32_t base = sb + s * STAGE_BYTES;
#pragma unroll
        for (int i = 0; i < 2; i++) {
            int u = tid + (i << 9);
            int r = u >> 3, sg = u & 7;
            uint32_t bo = (uint32_t)((r << 7) + (sg << 4));
            uint32_t sw = bo ^ ((bo >> 3) & 0x70);
            cp16(base + sw, Ab + (size_t)r * IN_F + kc + sg * 8);
            cp16(base + A_BYTES + sw, Bb + (size_t)r * IN_F + kc + sg * 8);
        }
    };

    // ldmatrix lane addressing (validated in round 2):
    // addr = base + ((frag_row_base + (grp&1)*8 + lr) * 128) + (grp>>1)*16,
    // then ^ (lr<<4) applies the SW128 swizzle (row&7 == lr here).
    const int grp = lane >> 3, lr = lane & 7;
    const uint32_t xorv = (uint32_t)(lr << 4);
    const uint32_t laneoff =
        (uint32_t)((((grp & 1) << 3) + lr) << 7) + (uint32_t)((grp >> 1) << 4);
    const uint32_t aoff0 = (uint32_t)((warp_m * 32) << 7) + laneoff;
    const uint32_t boff0 = (uint32_t)((warp_n * 32) << 7) + laneoff;

    // fp32 master accumulators: frag (mi in 0..1, nf in 0..3), 4 vals each
    float C[2][4][4];
#pragma unroll
    for (int a = 0; a < 2; a++)
#pragma unroll
        for (int b = 0; b < 4; b++)
#pragma unroll
            for (int d = 0; d < 4; d++) C[a][b][d] = 0.0f;

    // prologue: 2 chunks in flight
    issue(0);
    asm volatile("cp.async.commit_group;" ::: "memory");
    issue(1);
    asm volatile("cp.async.commit_group;" ::: "memory");

#pragma unroll 1
    for (int c = 0; c < KCHUNKS; c++) {
        asm volatile("cp.async.wait_group 1;" ::: "memory");
        __syncthreads();

        if (c + 2 < KCHUNKS) issue(c + 2);
        asm volatile("cp.async.commit_group;" ::: "memory");

        const uint32_t sa = sb + (c % NST) * STAGE_BYTES;
        const uint32_t sB = sa + A_BYTES;

        // fp16 accumulators live across a K=32 segment (2 k-steps)
        uint32_t Ch[2][4][2];
#pragma unroll
        for (int seg = 0; seg < 2; seg++) {
#pragma unroll
            for (int mi = 0; mi < 2; mi++)
#pragma unroll
                for (int nf = 0; nf < 4; nf++) {
                    Ch[mi][nf][0] = 0u;
                    Ch[mi][nf][1] = 0u;
                }
#pragma unroll
            for (int kk = 0; kk < 2; kk++) {
                const int ks = seg * 2 + kk;
                uint32_t af[2][4], bf[2][4];
#pragma unroll
                for (int mi = 0; mi < 2; mi++)
                    ldm_x4(af[mi], (sa + aoff0 + (uint32_t)(mi << 11) +
                                    (uint32_t)(ks << 5)) ^ xorv);
#pragma unroll
                for (int nj = 0; nj < 2; nj++)
                    ldm_x4(bf[nj], (sB + boff0 + (uint32_t)(nj << 11) +
                                    (uint32_t)(ks << 5)) ^ xorv);
#pragma unroll
                for (int mi = 0; mi < 2; mi++)
#pragma unroll
                    for (int nj = 0; nj < 2; nj++) {
                        mma16816_f16(Ch[mi][2 * nj + 0][0], Ch[mi][2 * nj + 0][1],
                                     af[mi], bf[nj][0], bf[nj][2]);
                        mma16816_f16(Ch[mi][2 * nj + 1][0], Ch[mi][2 * nj + 1][1],
                                     af[mi], bf[nj][1], bf[nj][3]);
                    }
            }
            // promote segment partials into fp32 masters
#pragma unroll
            for (int mi = 0; mi < 2; mi++)
#pragma unroll
                for (int nf = 0; nf < 4; nf++) {
                    float2 lo = __half22float2(
                        *reinterpret_cast<__half2*>(&Ch[mi][nf][0]));
                    float2 hi = __half22float2(
                        *reinterpret_cast<__half2*>(&Ch[mi][nf][1]));
                    C[mi][nf][0] += lo.x;
                    C[mi][nf][1] += lo.y;
                    C[mi][nf][2] += hi.x;
                    C[mi][nf][3] += hi.y;
                }
        }
        __syncthreads();
    }

    // epilogue: frag (mi, nf): rows row0+warp_m*32+mi*16+{g, g+8},
    // cols col0+warp_n*32+nf*8+q*2 (+1)
    const int g = lane >> 2, q = lane & 3;
    const int rbase = row0 + warp_m * 32 + g;
    const int cbase = col0 + warp_n * 32 + q * 2;
    float2 bv[4];
#pragma unroll
    for (int nf = 0; nf < 4; nf++) {
        bv[nf].x = __ldg(bias + cbase + nf * 8);
        bv[nf].y = __ldg(bias + cbase + nf * 8 + 1);
    }
#pragma unroll
    for (int mi = 0; mi < 2; mi++) {
        const int r_lo = rbase + mi * 16;
#pragma unroll
        for (int nf = 0; nf < 4; nf++) {
            const int cc = cbase + nf * 8;
            float2 v0, v1;
            v0.x = C[mi][nf][0] + bv[nf].x;
            v0.y = C[mi][nf][1] + bv[nf].y;
            v1.x = C[mi][nf][2] + bv[nf].x;
            v1.y = C[mi][nf][3] + bv[nf].y;
            *reinterpret_cast<float2*>(out + (size_t)r_lo * OUT_F + cc) = v0;
            *reinterpret_cast<float2*>(out + (size_t)(r_lo + 8) * OUT_F + cc) = v1;
        }
    }
}

// ---------------------------------------------------------------------------
// launch
// ---------------------------------------------------------------------------
extern "C" void kernel_launch(void* const* d_in, const int* in_sizes, int n_in,
                              void* d_out, int out_size) {
    const float* x      = (const float*)d_in[0];
    const int*   packed = (const int*)d_in[1];
    const float* absmax = (const float*)d_in[2];
    const float* bias   = (const float*)d_in[3];
    float* out = (float*)d_out;

    cvt_kernel<<<(MROWS * IN_F / 4) / 256, 256>>>(x);
    dequant_kernel<<<(PACKED_N / 4) / 256, 256>>>(packed, absmax);

    cudaFuncSetAttribute(gemm_kernel,
                         cudaFuncAttributeMaxDynamicSharedMemorySize, SMEM_BYTES);
    dim3 grid(OUT_F / BN, MROWS / BM);  // (86, 16)
    gemm_kernel<<<grid, 512, SMEM_BYTES>>>(bias, out);
}

// round 4
// speedup vs baseline: 1.2935x; 1.2935x over previous
#include <cuda_runtime.h>
#include <cuda_fp16.h>
#include <cstdint>

// Problem dims
#define IN_F   4096
#define OUT_F  11008
#define MROWS  2048
#define NUMEL  (IN_F * OUT_F)        // 45,088,768
#define PACKED_N (NUMEL / 2)         // 22,544,384

// GEMM tiling
#define BM 256
#define BN 128
#define BK 64
#define KCHUNKS (IN_F / BK)          // 64
#define NST 4
#define A_BYTES (BM * 128)           // 32768 (256 rows x 128B)
#define B_BYTES (BN * 128)           // 16384
#define STAGE_BYTES (A_BYTES + B_BYTES)   // 49152
#define SMEM_BYTES (NST * STAGE_BYTES)    // 196608

// prep kernel split
#define CVT_BLOCKS ((MROWS * IN_F / 4) / 256)   // 8192
#define DEQ_BLOCKS ((PACKED_N / 4) / 256)       // 22016

// Scratch (device globals; no allocation allowed)
__device__ __half g_W[NUMEL];          // dequantized W, row-major [OUT_F][IN_F]
__device__ __half g_X[MROWS * IN_F];   // fp16 x

__constant__ float c_nf4[16] = {
    -1.0f, -0.6961928009986877f, -0.5250730514526367f, -0.39491748809814453f,
    -0.28444138169288635f, -0.18477343022823334f, -0.09105003625154495f, 0.0f,
    0.07958029955625534f, 0.16093020141124725f, 0.24611230194568634f,
    0.33791524171829224f, 0.44070982933044434f, 0.5626170039176941f,
    0.7229568362236023f, 1.0f};

// ---------------------------------------------------------------------------
// fused prep: blocks [0, CVT_BLOCKS) convert x fp32->fp16,
//             blocks [CVT_BLOCKS, CVT_BLOCKS+DEQ_BLOCKS) dequant NF4 -> fp16 W
// ---------------------------------------------------------------------------
__global__ void prep_kernel(const float* __restrict__ x,
                            const int* __restrict__ packed,
                            const float* __restrict__ absmax) {
    const int b = blockIdx.x;
    if (b < CVT_BLOCKS) {
        int i = b * 256 + threadIdx.x;                    // handles 4 floats
        float4 v = reinterpret_cast<const float4*>(x)[i];
        __half2* o = reinterpret_cast<__half2*>(g_X);
        o[2 * i]     = __floats2half2_rn(v.x, v.y);
        o[2 * i + 1] = __floats2half2_rn(v.z, v.w);
    } else {
        int i = (b - CVT_BLOCKS) * 256 + threadIdx.x;     // handles packed[4i..4i+3]
        int4 pk = reinterpret_cast<const int4*>(packed)[i];
        float s = absmax[i >> 3];                          // (4i)/32 == i/8
        int v[4] = {pk.x, pk.y, pk.z, pk.w};
        __half h[8];
#pragma unroll
        for (int j = 0; j < 4; j++) {
            h[2 * j]     = __float2half_rn(c_nf4[(v[j] >> 4) & 0xF] * s);
            h[2 * j + 1] = __float2half_rn(c_nf4[v[j] & 0xF] * s);
        }
        reinterpret_cast<uint4*>(g_W)[i] = *reinterpret_cast<uint4*>(h);
    }
}

// ---------------------------------------------------------------------------
// PTX helpers
// ---------------------------------------------------------------------------
__device__ __forceinline__ uint32_t smem_u32(const void* p) {
    uint32_t a;
    asm("{ .reg .u64 t; cvta.to.shared.u64 t, %1; cvt.u32.u64 %0, t; }"
        : "=r"(a) : "l"(p));
    return a;
}

__device__ __forceinline__ void cp16(uint32_t saddr, const void* gaddr) {
    asm volatile("cp.async.cg.shared.global [%0], [%1], 16;"
                 :: "r"(saddr), "l"(gaddr));
}

__device__ __forceinline__ void ldm_x4(uint32_t* r, uint32_t addr) {
    asm volatile("ldmatrix.sync.aligned.m8n8.x4.shared.b16 {%0,%1,%2,%3}, [%4];"
                 : "=r"(r[0]), "=r"(r[1]), "=r"(r[2]), "=r"(r[3]) : "r"(addr));
}

__device__ __forceinline__ void mma16816(float* c, const uint32_t* a,
                                         uint32_t b0, uint32_t b1) {
    asm volatile(
        "mma.sync.aligned.m16n8k16.row.col.f32.f16.f16.f32 "
        "{%0,%1,%2,%3}, {%4,%5,%6,%7}, {%8,%9}, {%0,%1,%2,%3};"
        : "+f"(c[0]), "+f"(c[1]), "+f"(c[2]), "+f"(c[3])
        : "r"(a[0]), "r"(a[1]), "r"(a[2]), "r"(a[3]), "r"(b0), "r"(b1));
}

// ---------------------------------------------------------------------------
// GEMM: out[256,128] tile = A[256,K] * B[128,K]^T + bias, fp16 in / fp32 acc.
// 256 threads = 8 warps in 4(m) x 2(n); warp tile 64x64.
// 4-stage cp.async ring, prefetch distance 2, ONE __syncthreads per chunk
// (overwritten stage (c+2)%4 == (c-2)%4 was drained before sync(c)).
// SW128-swizzled 128B smem rows, ldmatrix.x4 feeds mma.sync.m16n8k16.
// ---------------------------------------------------------------------------
__global__ void __launch_bounds__(256)
gemm_kernel(const float* __restrict__ bias, float* __restrict__ out) {
    extern __shared__ char smem[];
    const uint32_t sb = smem_u32(smem);
    const int tid = threadIdx.x;
    const int wid = tid >> 5;
    const int lane = tid & 31;
    const int warp_m = wid >> 1;          // 0..3
    const int warp_n = wid & 1;           // 0..1
    const int row0 = blockIdx.y * BM;
    const int col0 = blockIdx.x * BN;

    const __half* Ab = g_X + (size_t)row0 * IN_F;
    const __half* Bb = g_W + (size_t)col0 * IN_F;

    // cp.async of chunk c into stage c%4
    auto issue = [&](int c) {
        const int s = c & (NST - 1);
        const int kc = c * BK;
        const uint32_t base = sb + s * STAGE_BYTES;
#pragma unroll
        for (int i = 0; i < 8; i++) {     // A: 2048 16B units / 256 thr
            int u = tid + (i << 8);
            int r = u >> 3, sg = u & 7;
            uint32_t bo = (uint32_t)((r << 7) + (sg << 4));
            uint32_t sw = bo ^ ((bo >> 3) & 0x70);
            cp16(base + sw, Ab + (size_t)r * IN_F + kc + sg * 8);
        }
#pragma unroll
        for (int i = 0; i < 4; i++) {     // B: 1024 units / 256 thr
            int u = tid + (i << 8);
            int r = u >> 3, sg = u & 7;
            uint32_t bo = (uint32_t)((r << 7) + (sg << 4));
            uint32_t sw = bo ^ ((bo >> 3) & 0x70);
            cp16(base + A_BYTES + sw, Bb + (size_t)r * IN_F + kc + sg * 8);
        }
    };

    // per-thread ldmatrix lane addressing (SW128; validated round 2)
    const int grp = lane >> 3, lr = lane & 7;
    const uint32_t xorv = (uint32_t)(lr << 4);
    const uint32_t laneoff =
        (uint32_t)((((grp & 1) << 3) + lr) << 7) + (uint32_t)((grp >> 1) << 4);
    const uint32_t aoff0 = (uint32_t)((warp_m * 64) << 7) + laneoff;
    const uint32_t boff0 = (uint32_t)((warp_n * 64) << 7) + laneoff;

    float C[4][8][4];
#pragma unroll
    for (int a = 0; a < 4; a++)
#pragma unroll
        for (int b = 0; b < 8; b++)
#pragma unroll
            for (int d = 0; d < 4; d++) C[a][b][d] = 0.0f;

    // prologue: 2 chunks in flight
    issue(0);
    asm volatile("cp.async.commit_group;" ::: "memory");
    issue(1);
    asm volatile("cp.async.commit_group;" ::: "memory");

#pragma unroll 1
    for (int c = 0; c < KCHUNKS; c++) {
        asm volatile("cp.async.wait_group 1;" ::: "memory");
        __syncthreads();

        if (c + 2 < KCHUNKS) issue(c + 2);
        asm volatile("cp.async.commit_group;" ::: "memory");

        const uint32_t sa = sb + (c & (NST - 1)) * STAGE_BYTES;
        const uint32_t sB = sa + A_BYTES;
#pragma unroll
        for (int ks = 0; ks < 4; ks++) {
            uint32_t af[4][4], bf[4][4];
#pragma unroll
            for (int mi = 0; mi < 4; mi++)
                ldm_x4(af[mi], (sa + aoff0 + (uint32_t)(mi << 11) +
                                (uint32_t)(ks << 5)) ^ xorv);
#pragma unroll
            for (int nj = 0; nj < 4; nj++)
                ldm_x4(bf[nj], (sB + boff0 + (uint32_t)(nj << 11) +
                                (uint32_t)(ks << 5)) ^ xorv);
#pragma unroll
            for (int mi = 0; mi < 4; mi++)
#pragma unroll
                for (int nj = 0; nj < 4; nj++) {
                    mma16816(C[mi][2 * nj + 0], af[mi], bf[nj][0], bf[nj][2]);
                    mma16816(C[mi][2 * nj + 1], af[mi], bf[nj][1], bf[nj][3]);
                }
        }
        // no trailing sync: next iteration's sync precedes any stage reuse
    }

    // epilogue: D frag (mi, nf): rows row0+warp_m*64+mi*16+{g, g+8},
    // cols col0+warp_n*64+nf*8+q*2 (+1)
    const int g = lane >> 2, q = lane & 3;
    const int rbase = row0 + warp_m * 64 + g;
    const int cbase = col0 + warp_n * 64 + q * 2;
    float2 bv[8];
#pragma unroll
    for (int nf = 0; nf < 8; nf++) {
        bv[nf].x = __ldg(bias + cbase + nf * 8);
        bv[nf].y = __ldg(bias + cbase + nf * 8 + 1);
    }
#pragma unroll
    for (int mi = 0; mi < 4; mi++) {
        const int r_lo = rbase + mi * 16;
#pragma unroll
        for (int nf = 0; nf < 8; nf++) {
            const int cc = cbase + nf * 8;
            float2 v0, v1;
            v0.x = C[mi][nf][0] + bv[nf].x;
            v0.y = C[mi][nf][1] + bv[nf].y;
            v1.x = C[mi][nf][2] + bv[nf].x;
            v1.y = C[mi][nf][3] + bv[nf].y;
            *reinterpret_cast<float2*>(out + (size_t)r_lo * OUT_F + cc) = v0;
            *reinterpret_cast<float2*>(out + (size_t)(r_lo + 8) * OUT_F + cc) = v1;
        }
    }
}

// ---------------------------------------------------------------------------
// launch
// ---------------------------------------------------------------------------
extern "C" void kernel_launch(void* const* d_in, const int* in_sizes, int n_in,
                              void* d_out, int out_size) {
    const float* x      = (const float*)d_in[0];
    const int*   packed = (const int*)d_in[1];
    const float* absmax = (const float*)d_in[2];
    const float* bias   = (const float*)d_in[3];
    float* out = (float*)d_out;

    prep_kernel<<<CVT_BLOCKS + DEQ_BLOCKS, 256>>>(x, packed, absmax);

    cudaFuncSetAttribute(gemm_kernel,
                         cudaFuncAttributeMaxDynamicSharedMemorySize, SMEM_BYTES);
    dim3 grid(OUT_F / BN, MROWS / BM);  // (86, 8)
    gemm_kernel<<<grid, 256, SMEM_BYTES>>>(bias, out);
}

// round 5
// speedup vs baseline: 1.3035x; 1.0078x over previous
#include <cuda_runtime.h>
#include <cuda_fp16.h>
#include <cstdint>

// Problem dims
#define IN_F   4096
#define OUT_F  11008
#define MROWS  2048
#define NUMEL  (IN_F * OUT_F)        // 45,088,768
#define PACKED_N (NUMEL / 2)         // 22,544,384

// GEMM tiling
#define BM 256
#define BN 128
#define BK 64
#define KCHUNKS (IN_F / BK)          // 64
#define NST 4
#define A_BYTES (BM * 128)           // 32768 (256 rows x 128B)
#define B_BYTES (BN * 128)           // 16384
#define STAGE_BYTES (A_BYTES + B_BYTES)   // 49152
#define SMEM_BYTES (NST * STAGE_BYTES)    // 196608

// prep kernel split
#define CVT_BLOCKS ((MROWS * IN_F / 4) / 256)   // 8192
#define DEQ_BLOCKS ((PACKED_N / 4) / 256)       // 22016

// Scratch (device globals; no allocation allowed)
__device__ __half g_W[NUMEL];          // dequantized W, row-major [OUT_F][IN_F]
__device__ __half g_X[MROWS * IN_F];   // fp16 x

__constant__ float c_nf4[16] = {
    -1.0f, -0.6961928009986877f, -0.5250730514526367f, -0.39491748809814453f,
    -0.28444138169288635f, -0.18477343022823334f, -0.09105003625154495f, 0.0f,
    0.07958029955625534f, 0.16093020141124725f, 0.24611230194568634f,
    0.33791524171829224f, 0.44070982933044434f, 0.5626170039176941f,
    0.7229568362236023f, 1.0f};

// ---------------------------------------------------------------------------
// fused prep: blocks [0, CVT_BLOCKS) convert x fp32->fp16,
//             blocks [CVT_BLOCKS, ...) dequant NF4 -> fp16 W
// ---------------------------------------------------------------------------
__global__ void prep_kernel(const float* __restrict__ x,
                            const int* __restrict__ packed,
                            const float* __restrict__ absmax) {
    const int b = blockIdx.x;
    if (b < CVT_BLOCKS) {
        int i = b * 256 + threadIdx.x;                    // handles 4 floats
        float4 v = reinterpret_cast<const float4*>(x)[i];
        __half2* o = reinterpret_cast<__half2*>(g_X);
        o[2 * i]     = __floats2half2_rn(v.x, v.y);
        o[2 * i + 1] = __floats2half2_rn(v.z, v.w);
    } else {
        int i = (b - CVT_BLOCKS) * 256 + threadIdx.x;     // packed[4i..4i+3]
        int4 pk = reinterpret_cast<const int4*>(packed)[i];
        float s = absmax[i >> 3];                          // (4i)/32 == i/8
        int v[4] = {pk.x, pk.y, pk.z, pk.w};
        __half h[8];
#pragma unroll
        for (int j = 0; j < 4; j++) {
            h[2 * j]     = __float2half_rn(c_nf4[(v[j] >> 4) & 0xF] * s);
            h[2 * j + 1] = __float2half_rn(c_nf4[v[j] & 0xF] * s);
        }
        reinterpret_cast<uint4*>(g_W)[i] = *reinterpret_cast<uint4*>(h);
    }
}

// ---------------------------------------------------------------------------
// PTX helpers
// ---------------------------------------------------------------------------
__device__ __forceinline__ uint32_t smem_u32(const void* p) {
    uint32_t a;
    asm("{ .reg .u64 t; cvta.to.shared.u64 t, %1; cvt.u32.u64 %0, t; }"
        : "=r"(a) : "l"(p));
    return a;
}

__device__ __forceinline__ void cp16(uint32_t saddr, const void* gaddr) {
    asm volatile("cp.async.cg.shared.global [%0], [%1], 16;"
                 :: "r"(saddr), "l"(gaddr));
}

__device__ __forceinline__ void ldm_x4(uint32_t* r, uint32_t addr) {
    asm volatile("ldmatrix.sync.aligned.m8n8.x4.shared.b16 {%0,%1,%2,%3}, [%4];"
                 : "=r"(r[0]), "=r"(r[1]), "=r"(r[2]), "=r"(r[3]) : "r"(addr));
}

__device__ __forceinline__ void mma16816(float* c, const uint32_t* a,
                                         uint32_t b0, uint32_t b1) {
    asm volatile(
        "mma.sync.aligned.m16n8k16.row.col.f32.f16.f16.f32 "
        "{%0,%1,%2,%3}, {%4,%5,%6,%7}, {%8,%9}, {%0,%1,%2,%3};"
        : "+f"(c[0]), "+f"(c[1]), "+f"(c[2]), "+f"(c[3])
        : "r"(a[0]), "r"(a[1]), "r"(a[2]), "r"(a[3]), "r"(b0), "r"(b1));
}

// ---------------------------------------------------------------------------
// GEMM: out[256,128] tile = A[256,K] * B[128,K]^T + bias, fp16 in / fp32 acc.
// 512 threads = 16 warps in 4(m) x 4(n); warp tile 64x32 -> 4 warps/SMSP to
// feed the HMMA pipe (round-4 ncu: tensor 52%, occ 12.5% with 8 warps).
// 4-stage cp.async ring, prefetch distance 3, ONE __syncthreads per chunk.
// SW128-swizzled 128B smem rows, ldmatrix.x4 feeds mma.sync.m16n8k16.
// ---------------------------------------------------------------------------
__global__ void __launch_bounds__(512, 1)
gemm_kernel(const float* __restrict__ bias, float* __restrict__ out) {
    extern __shared__ char smem[];
    const uint32_t sb = smem_u32(smem);
    const int tid = threadIdx.x;
    const int wid = tid >> 5;
    const int lane = tid & 31;
    const int warp_m = wid >> 2;          // 0..3 (64-row blocks)
    const int warp_n = wid & 3;           // 0..3 (32-col blocks)
    const int row0 = blockIdx.y * BM;
    const int col0 = blockIdx.x * BN;

    const __half* Ab = g_X + (size_t)row0 * IN_F;
    const __half* Bb = g_W + (size_t)col0 * IN_F;

    // cp.async of chunk c into stage c%4 (512 threads: A 4 units, B 2 units)
    auto issue = [&](int c) {
        const int s = c & (NST - 1);
        const int kc = c * BK;
        const uint32_t base = sb + s * STAGE_BYTES;
#pragma unroll
        for (int i = 0; i < 4; i++) {     // A: 2048 16B units / 512 thr
            int u = tid + (i << 9);
            int r = u >> 3, sg = u & 7;
            uint32_t bo = (uint32_t)((r << 7) + (sg << 4));
            uint32_t sw = bo ^ ((bo >> 3) & 0x70);
            cp16(base + sw, Ab + (size_t)r * IN_F + kc + sg * 8);
        }
#pragma unroll
        for (int i = 0; i < 2; i++) {     // B: 1024 units / 512 thr
            int u = tid + (i << 9);
            int r = u >> 3, sg = u & 7;
            uint32_t bo = (uint32_t)((r << 7) + (sg << 4));
            uint32_t sw = bo ^ ((bo >> 3) & 0x70);
            cp16(base + A_BYTES + sw, Bb + (size_t)r * IN_F + kc + sg * 8);
        }
    };

    // per-thread ldmatrix lane addressing (SW128; validated round 2)
    const int grp = lane >> 3, lr = lane & 7;
    const uint32_t xorv = (uint32_t)(lr << 4);
    const uint32_t laneoff =
        (uint32_t)((((grp & 1) << 3) + lr) << 7) + (uint32_t)((grp >> 1) << 4);
    const uint32_t aoff0 = (uint32_t)((warp_m * 64) << 7) + laneoff;
    const uint32_t boff0 = (uint32_t)((warp_n * 32) << 7) + laneoff;

    float C[4][4][4];
#pragma unroll
    for (int a = 0; a < 4; a++)
#pragma unroll
        for (int b = 0; b < 4; b++)
#pragma unroll
            for (int d = 0; d < 4; d++) C[a][b][d] = 0.0f;

    // prologue: 3 chunks in flight
    issue(0);
    asm volatile("cp.async.commit_group;" ::: "memory");
    issue(1);
    asm volatile("cp.async.commit_group;" ::: "memory");
    issue(2);
    asm volatile("cp.async.commit_group;" ::: "memory");

#pragma unroll 1
    for (int c = 0; c < KCHUNKS; c++) {
        asm volatile("cp.async.wait_group 2;" ::: "memory");
        __syncthreads();

        // stage (c+3)%4 == (c-1)%4 was fully consumed before this sync
        if (c + 3 < KCHUNKS) issue(c + 3);
        asm volatile("cp.async.commit_group;" ::: "memory");

        const uint32_t sa = sb + (c & (NST - 1)) * STAGE_BYTES;
        const uint32_t sB = sa + A_BYTES;
#pragma unroll
        for (int ks = 0; ks < 4; ks++) {
            uint32_t af[4][4], bf[2][4];
#pragma unroll
            for (int mi = 0; mi < 4; mi++)
                ldm_x4(af[mi], (sa + aoff0 + (uint32_t)(mi << 11) +
                                (uint32_t)(ks << 5)) ^ xorv);
#pragma unroll
            for (int nj = 0; nj < 2; nj++)
                ldm_x4(bf[nj], (sB + boff0 + (uint32_t)(nj << 11) +
                                (uint32_t)(ks << 5)) ^ xorv);
#pragma unroll
            for (int mi = 0; mi < 4; mi++)
#pragma unroll
                for (int nj = 0; nj < 2; nj++) {
                    mma16816(C[mi][2 * nj + 0], af[mi], bf[nj][0], bf[nj][2]);
                    mma16816(C[mi][2 * nj + 1], af[mi], bf[nj][1], bf[nj][3]);
                }
        }
        // no trailing sync: next iteration's sync precedes any stage reuse
    }

    // epilogue: D frag (mi, nf): rows row0+warp_m*64+mi*16+{g, g+8},
    // cols col0+warp_n*32+nf*8+q*2 (+1)
    const int g = lane >> 2, q = lane & 3;
    const int rbase = row0 + warp_m * 64 + g;
    const int cbase = col0 + warp_n * 32 + q * 2;
    float2 bv[4];
#pragma unroll
    for (int nf = 0; nf < 4; nf++) {
        bv[nf].x = __ldg(bias + cbase + nf * 8);
        bv[nf].y = __ldg(bias + cbase + nf * 8 + 1);
    }
#pragma unroll
    for (int mi = 0; mi < 4; mi++) {
        const int r_lo = rbase + mi * 16;
#pragma unroll
        for (int nf = 0; nf < 4; nf++) {
            const int cc = cbase + nf * 8;
            float2 v0, v1;
            v0.x = C[mi][nf][0] + bv[nf].x;
            v0.y = C[mi][nf][1] + bv[nf].y;
            v1.x = C[mi][nf][2] + bv[nf].x;
            v1.y = C[mi][nf][3] + bv[nf].y;
            *reinterpret_cast<float2*>(out + (size_t)r_lo * OUT_F + cc) = v0;
            *reinterpret_cast<float2*>(out + (size_t)(r_lo + 8) * OUT_F + cc) = v1;
        }
    }
}

// ---------------------------------------------------------------------------
// launch
// ---------------------------------------------------------------------------
extern "C" void kernel_launch(void* const* d_in, const int* in_sizes, int n_in,
                              void* d_out, int out_size) {
    const float* x      = (const float*)d_in[0];
    const int*   packed = (const int*)d_in[1];
    const float* absmax = (const float*)d_in[2];
    const float* bias   = (const float*)d_in[3];
    float* out = (float*)d_out;

    prep_kernel<<<CVT_BLOCKS + DEQ_BLOCKS, 256>>>(x, packed, absmax);

    cudaFuncSetAttribute(gemm_kernel,
                         cudaFuncAttributeMaxDynamicSharedMemorySize, SMEM_BYTES);
    dim3 grid(OUT_F / BN, MROWS / BM);  // (86, 8)
    gemm_kernel<<<grid, 512, SMEM_BYTES>>>(bias, out);
}

// round 6
// speedup vs baseline: 1.4820x; 1.1369x over previous
#include <cuda_runtime.h>
#include <cuda_fp16.h>
#include <cstdint>

// Problem dims
#define IN_F   4096
#define OUT_F  11008
#define MROWS  2048
#define NUMEL  (IN_F * OUT_F)        // 45,088,768
#define PACKED_N (NUMEL / 2)         // 22,544,384

// GEMM tiling
#define BM 256
#define BN 128
#define BK 64
#define KCHUNKS (IN_F / BK)          // 64
#define NST 4
#define A_BYTES (BM * 128)           // 32768 (256 rows x 128B)
#define B_BYTES (BN * 128)           // 16384
#define STAGE_BYTES (A_BYTES + B_BYTES)   // 49152
#define SMEM_BYTES (NST * STAGE_BYTES)    // 196608

// prep kernel split
#define CVT_BLOCKS ((MROWS * IN_F / 4) / 256)   // 8192
#define DEQ_BLOCKS ((PACKED_N / 4) / 256)       // 22016

// Scratch (device globals; no allocation allowed)
__device__ __half g_W[NUMEL];          // dequantized W, row-major [OUT_F][IN_F]
__device__ __half g_X[MROWS * IN_F];   // fp16 x

__constant__ float c_nf4[16] = {
    -1.0f, -0.6961928009986877f, -0.5250730514526367f, -0.39491748809814453f,
    -0.28444138169288635f, -0.18477343022823334f, -0.09105003625154495f, 0.0f,
    0.07958029955625534f, 0.16093020141124725f, 0.24611230194568634f,
    0.33791524171829224f, 0.44070982933044434f, 0.5626170039176941f,
    0.7229568362236023f, 1.0f};

// ---------------------------------------------------------------------------
// fused prep: blocks [0, CVT_BLOCKS) convert x fp32->fp16,
//             blocks [CVT_BLOCKS, ...) dequant NF4 -> fp16 W.
// Dequant uses a 32x-replicated smem LUT: addr = code*32 + lane -> bank==lane,
// conflict-free for ANY code pattern (fixes divergent-LDC replay storms).
// ---------------------------------------------------------------------------
__global__ void prep_kernel(const float* __restrict__ x,
                            const int* __restrict__ packed,
                            const float* __restrict__ absmax) {
    __shared__ float lut[16 * 32];
    const int b = blockIdx.x;
    const int tid = threadIdx.x;
    if (b < CVT_BLOCKS) {
        int i = b * 256 + tid;                            // handles 4 floats
        float4 v = reinterpret_cast<const float4*>(x)[i];
        __half2* o = reinterpret_cast<__half2*>(g_X);
        o[2 * i]     = __floats2half2_rn(v.x, v.y);
        o[2 * i + 1] = __floats2half2_rn(v.z, v.w);
    } else {
        lut[tid]       = c_nf4[tid >> 5];                 // uniform index: no replay
        lut[tid + 256] = c_nf4[(tid + 256) >> 5];
        __syncthreads();
        const int lane = tid & 31;
        int i = (b - CVT_BLOCKS) * 256 + tid;             // packed[4i..4i+3]
        int4 pk = reinterpret_cast<const int4*>(packed)[i];
        float s = absmax[i >> 3];                          // (4i)/32 == i/8
        int v[4] = {pk.x, pk.y, pk.z, pk.w};
        __half h[8];
#pragma unroll
        for (int j = 0; j < 4; j++) {
            float whi = lut[((v[j] >> 4) & 0xF) * 32 + lane];
            float wlo = lut[(v[j] & 0xF) * 32 + lane];
            h[2 * j]     = __float2half_rn(whi * s);
            h[2 * j + 1] = __float2half_rn(wlo * s);
        }
        reinterpret_cast<uint4*>(g_W)[i] = *reinterpret_cast<uint4*>(h);
    }
}

// ---------------------------------------------------------------------------
// PTX helpers
// ---------------------------------------------------------------------------
__device__ __forceinline__ uint32_t smem_u32(const void* p) {
    uint32_t a;
    asm("{ .reg .u64 t; cvta.to.shared.u64 t, %1; cvt.u32.u64 %0, t; }"
        : "=r"(a) : "l"(p));
    return a;
}

__device__ __forceinline__ void cp16(uint32_t saddr, const void* gaddr) {
    asm volatile("cp.async.cg.shared.global [%0], [%1], 16;"
                 :: "r"(saddr), "l"(gaddr));
}

__device__ __forceinline__ void ldm_x4(uint32_t* r, uint32_t addr) {
    asm volatile("ldmatrix.sync.aligned.m8n8.x4.shared.b16 {%0,%1,%2,%3}, [%4];"
                 : "=r"(r[0]), "=r"(r[1]), "=r"(r[2]), "=r"(r[3]) : "r"(addr));
}

// fp16-accumulate mma: {c0,c1} (4 halves) += A * B
__device__ __forceinline__ void mma16816_f16(uint32_t& c0, uint32_t& c1,
                                             const uint32_t* a,
                                             uint32_t b0, uint32_t b1) {
    asm volatile(
        "mma.sync.aligned.m16n8k16.row.col.f16.f16.f16.f16 "
        "{%0,%1}, {%2,%3,%4,%5}, {%6,%7}, {%0,%1};"
        : "+r"(c0), "+r"(c1)
        : "r"(a[0]), "r"(a[1]), "r"(a[2]), "r"(a[3]), "r"(b0), "r"(b1));
}

// ---------------------------------------------------------------------------
// GEMM: out[256,128] tile = A[256,K] * B[128,K]^T + bias.
// Round-4 tiling (256 thr, 8 warps 4x2, warp tile 64x64, best LDSM:HMMA
// ratio), but fp16 mma accumulation across each BK=64 chunk, promoted to
// fp32 master accumulators once per chunk. 4-stage cp.async ring, prefetch
// distance 2, one __syncthreads per chunk.
// ---------------------------------------------------------------------------
__global__ void __launch_bounds__(256, 1)
gemm_kernel(const float* __restrict__ bias, float* __restrict__ out) {
    extern __shared__ char smem[];
    const uint32_t sb = smem_u32(smem);
    const int tid = threadIdx.x;
    const int wid = tid >> 5;
    const int lane = tid & 31;
    const int warp_m = wid >> 1;          // 0..3
    const int warp_n = wid & 1;           // 0..1
    const int row0 = blockIdx.y * BM;
    const int col0 = blockIdx.x * BN;

    const __half* Ab = g_X + (size_t)row0 * IN_F;
    const __half* Bb = g_W + (size_t)col0 * IN_F;

    // cp.async of chunk c into stage c%4
    auto issue = [&](int c) {
        const int s = c & (NST - 1);
        const int kc = c * BK;
        const uint32_t base = sb + s * STAGE_BYTES;
#pragma unroll
        for (int i = 0; i < 8; i++) {     // A: 2048 16B units / 256 thr
            int u = tid + (i << 8);
            int r = u >> 3, sg = u & 7;
            uint32_t bo = (uint32_t)((r << 7) + (sg << 4));
            uint32_t sw = bo ^ ((bo >> 3) & 0x70);
            cp16(base + sw, Ab + (size_t)r * IN_F + kc + sg * 8);
        }
#pragma unroll
        for (int i = 0; i < 4; i++) {     // B: 1024 units / 256 thr
            int u = tid + (i << 8);
            int r = u >> 3, sg = u & 7;
            uint32_t bo = (uint32_t)((r << 7) + (sg << 4));
            uint32_t sw = bo ^ ((bo >> 3) & 0x70);
            cp16(base + A_BYTES + sw, Bb + (size_t)r * IN_F + kc + sg * 8);
        }
    };

    // per-thread ldmatrix lane addressing (SW128; validated round 2)
    const int grp = lane >> 3, lr = lane & 7;
    const uint32_t xorv = (uint32_t)(lr << 4);
    const uint32_t laneoff =
        (uint32_t)((((grp & 1) << 3) + lr) << 7) + (uint32_t)((grp >> 1) << 4);
    const uint32_t aoff0 = (uint32_t)((warp_m * 64) << 7) + laneoff;
    const uint32_t boff0 = (uint32_t)((warp_n * 64) << 7) + laneoff;

    // fp32 master accumulators
    float C[4][8][4];
#pragma unroll
    for (int a = 0; a < 4; a++)
#pragma unroll
        for (int b = 0; b < 8; b++)
#pragma unroll
            for (int d = 0; d < 4; d++) C[a][b][d] = 0.0f;

    // prologue: 2 chunks in flight
    issue(0);
    asm volatile("cp.async.commit_group;" ::: "memory");
    issue(1);
    asm volatile("cp.async.commit_group;" ::: "memory");

#pragma unroll 1
    for (int c = 0; c < KCHUNKS; c++) {
        asm volatile("cp.async.wait_group 1;" ::: "memory");
        __syncthreads();

        if (c + 2 < KCHUNKS) issue(c + 2);
        asm volatile("cp.async.commit_group;" ::: "memory");

        const uint32_t sa = sb + (c & (NST - 1)) * STAGE_BYTES;
        const uint32_t sB = sa + A_BYTES;

        // fp16 accumulators live across the whole K=64 chunk
        uint32_t Ch[4][8][2];
#pragma unroll
        for (int mi = 0; mi < 4; mi++)
#pragma unroll
            for (int nf = 0; nf < 8; nf++) {
                Ch[mi][nf][0] = 0u;
                Ch[mi][nf][1] = 0u;
            }

#pragma unroll
        for (int ks = 0; ks < 4; ks++) {
            uint32_t af[4][4], bf[4][4];
#pragma unroll
            for (int mi = 0; mi < 4; mi++)
                ldm_x4(af[mi], (sa + aoff0 + (uint32_t)(mi << 11) +
                                (uint32_t)(ks << 5)) ^ xorv);
#pragma unroll
            for (int nj = 0; nj < 4; nj++)
                ldm_x4(bf[nj], (sB + boff0 + (uint32_t)(nj << 11) +
                                (uint32_t)(ks << 5)) ^ xorv);
#pragma unroll
            for (int mi = 0; mi < 4; mi++)
#pragma unroll
                for (int nj = 0; nj < 4; nj++) {
                    mma16816_f16(Ch[mi][2 * nj + 0][0], Ch[mi][2 * nj + 0][1],
                                 af[mi], bf[nj][0], bf[nj][2]);
                    mma16816_f16(Ch[mi][2 * nj + 1][0], Ch[mi][2 * nj + 1][1],
                                 af[mi], bf[nj][1], bf[nj][3]);
                }
        }

        // promote chunk partials into fp32 masters (once per BK=64)
#pragma unroll
        for (int mi = 0; mi < 4; mi++)
#pragma unroll
            for (int nf = 0; nf < 8; nf++) {
                float2 lo = __half22float2(
                    *reinterpret_cast<__half2*>(&Ch[mi][nf][0]));
                float2 hi = __half22float2(
                    *reinterpret_cast<__half2*>(&Ch[mi][nf][1]));
                C[mi][nf][0] += lo.x;
                C[mi][nf][1] += lo.y;
                C[mi][nf][2] += hi.x;
                C[mi][nf][3] += hi.y;
            }
        // no trailing sync: next iteration's sync precedes any stage reuse
    }

    // epilogue: D frag (mi, nf): rows row0+warp_m*64+mi*16+{g, g+8},
    // cols col0+warp_n*64+nf*8+q*2 (+1)
    const int g = lane >> 2, q = lane & 3;
    const int rbase = row0 + warp_m * 64 + g;
    const int cbase = col0 + warp_n * 64 + q * 2;
    float2 bv[8];
#pragma unroll
    for (int nf = 0; nf < 8; nf++) {
        bv[nf].x = __ldg(bias + cbase + nf * 8);
        bv[nf].y = __ldg(bias + cbase + nf * 8 + 1);
    }
#pragma unroll
    for (int mi = 0; mi < 4; mi++) {
        const int r_lo = rbase + mi * 16;
#pragma unroll
        for (int nf = 0; nf < 8; nf++) {
            const int cc = cbase + nf * 8;
            float2 v0, v1;
            v0.x = C[mi][nf][0] + bv[nf].x;
            v0.y = C[mi][nf][1] + bv[nf].y;
            v1.x = C[mi][nf][2] + bv[nf].x;
            v1.y = C[mi][nf][3] + bv[nf].y;
            *reinterpret_cast<float2*>(out + (size_t)r_lo * OUT_F + cc) = v0;
            *reinterpret_cast<float2*>(out + (size_t)(r_lo + 8) * OUT_F + cc) = v1;
        }
    }
}

// ---------------------------------------------------------------------------
// launch
// ---------------------------------------------------------------------------
extern "C" void kernel_launch(void* const* d_in, const int* in_sizes, int n_in,
                              void* d_out, int out_size) {
    const float* x      = (const float*)d_in[0];
    const int*   packed = (const int*)d_in[1];
    const float* absmax = (const float*)d_in[2];
    const float* bias   = (const float*)d_in[3];
    float* out = (float*)d_out;

    prep_kernel<<<CVT_BLOCKS + DEQ_BLOCKS, 256>>>(x, packed, absmax);

    cudaFuncSetAttribute(gemm_kernel,
                         cudaFuncAttributeMaxDynamicSharedMemorySize, SMEM_BYTES);
    dim3 grid(OUT_F / BN, MROWS / BM);  // (86, 8)
    gemm_kernel<<<grid, 256, SMEM_BYTES>>>(bias, out);
}